// round 9
// baseline (speedup 1.0000x reference)
#include <cuda_runtime.h>
#include <cuda_fp16.h>
#include <stdint.h>

// Problem constants (this problem: B=1024, N=1024, T1=20000, T2=60000)
#define N_SP      1024
#define STRIDE    1025                      // half2 units; 1025 % 32 == 1 -> conflict-free
#define CAP       256                       // fixed bucket capacity per species (mean 78)
#define ROWS_PER_CTA 64                     // 32 row-PAIRS, one pair per lane (half2)
#define PAIRS     32
#define C_SPLIT   8                         // column splits per row-group
#define COLS_PER_CTA  (N_SP / C_SPLIT)      // 128
#define COLS_PER_WARP (COLS_PER_CTA / 32)   // 4
#define SMEM_BYTES (PAIRS * STRIDE * 4)     // 131200 B (half2 = 4B)

// __device__ scratch (allocation-free per harness rules)
__device__ int d_cursor[N_SP];              // per-species fill count
// packed records: {rate_bits_f32, (ia*4) | (ib*4)<<16}.
// Slots >= cnt are NEVER written by any run -> stay zero-initialized ->
// zero-rate pad records are safe to process (contribute exactly 0).
// +16 pad entries for one-past-end prefetch of the last slab.
__device__ __align__(16) uint2 d_rec[N_SP * CAP + 16];

// ---------------- prep: bucketed scatter (4 terms/thread for MLP) ----------------
__global__ void scatterK(const float* __restrict__ r1, const float* __restrict__ r2,
                         const float* __restrict__ dn,
                         const int* __restrict__ ir1,
                         const int* __restrict__ ir2a, const int* __restrict__ ir2b,
                         const int* __restrict__ io1, const int* __restrict__ io2,
                         int T1, int T2) {
    int t0 = (blockIdx.x * blockDim.x + threadIdx.x) * 4;
    int T = T1 + T2;
    float dnv = dn[0];
#pragma unroll
    for (int j = 0; j < 4; ++j) {
        int t = t0 + j;
        if (t >= T) break;
        float rate; int ia, ib, o;
        if (t < T1) {            // 1st-order: y[ia] * 1.0 (constant slot at index N_SP)
            rate = r1[t]; ia = ir1[t]; ib = N_SP; o = io1[t];
        } else {                 // 2nd-order: den_norm folded into rate
            int u = t - T1;
            rate = r2[u] * dnv; ia = ir2a[u]; ib = ir2b[u]; o = io2[u];
        }
        int pos = atomicAdd(&d_cursor[o], 1);
        if (pos < CAP)           // capacity guard (never hit for this problem's stats)
            d_rec[o * CAP + pos] = make_uint2(__float_as_uint(rate),
                                              (uint32_t)(ia * 4) | ((uint32_t)(ib * 4) << 16));
    }
}

// ---------------- main: gather kernel (fp16 row-pair, 4-column interleaved) -------
// CTA = (row-group of 64 batch rows) x (column partition of 128 species).
// Lane = row-pair: y_sh[lane][spec] = half2(y[2*lane][spec], y[2*lane+1][spec]).
// Warp walks its 4 columns' record streams IN LOCKSTEP: 4 independent uniform
// LDG.128 + 16 independent LDS per iteration -> deep MLP, branch-free body.

__device__ __forceinline__ void term2(const char* rowp, uint32_t rate_bits,
                                      uint32_t off, float& accA, float& accB) {
    __half2 va = *(const __half2*)(rowp + (off & 0xFFFFu));
    __half2 vb = *(const __half2*)(rowp + (off >> 16));
    float2 pf = __half22float2(__hmul2(va, vb));
    float r = __uint_as_float(rate_bits);
    accA = fmaf(r, pf.x, accA);
    accB = fmaf(r, pf.y, accB);
}

__global__ __launch_bounds__(1024, 1)
void mainK(const float* __restrict__ y, float* __restrict__ out) {
    extern __shared__ __align__(16) char smem_raw[];
    __half2* y_sh = (__half2*)smem_raw;     // PAIRS * STRIDE half2
    int rg    = blockIdx.x / C_SPLIT;
    int cpart = blockIdx.x % C_SPLIT;
    int tid   = threadIdx.x;
    int lane  = tid & 31, w = tid >> 5;
    int cbase = cpart * COLS_PER_CTA + w * COLS_PER_WARP;

    // Prefetch the warp's 4 column lengths (overlaps with smem fill).
    int nvec[COLS_PER_WARP];    // uint4 count per column (2 records each)
    int nmax = 0;
#pragma unroll
    for (int c = 0; c < COLS_PER_WARP; ++c) {
        int cnt = d_cursor[cbase + c];
        cnt = cnt < CAP ? cnt : CAP;
        nvec[c] = (cnt + 1) >> 1;
        nmax = nvec[c] > nmax ? nvec[c] : nmax;
    }
    // NOTE: columns shorter than nmax consume zero-rate pads (see d_rec comment).

    // Fill: float4 loads per row of the pair -> 4 half2 -> scalar STS (stride 1025).
    const float4* yb4 = (const float4*)(y + (size_t)rg * ROWS_PER_CTA * N_SP);
#pragma unroll
    for (int idx = tid; idx < PAIRS * N_SP / 4; idx += 1024) {
        int pair = idx >> 8;                       // 256 float4-slots per row
        int s4   = idx & 255;
        float4 a = yb4[(2 * pair)     * (N_SP / 4) + s4];
        float4 b = yb4[(2 * pair + 1) * (N_SP / 4) + s4];
        __half2* dst = y_sh + pair * STRIDE + s4 * 4;
        dst[0] = __floats2half2_rn(a.x, b.x);
        dst[1] = __floats2half2_rn(a.y, b.y);
        dst[2] = __floats2half2_rn(a.z, b.z);
        dst[3] = __floats2half2_rn(a.w, b.w);
    }
    if (tid < 32) y_sh[tid * STRIDE + N_SP] = __floats2half2_rn(1.f, 1.f);
    __syncthreads();

    const char* rowp = (const char*)(y_sh + lane * STRIDE);

    const uint4* rp[COLS_PER_WARP];
    uint4 cur[COLS_PER_WARP];
    float accA[COLS_PER_WARP], accB[COLS_PER_WARP];
#pragma unroll
    for (int c = 0; c < COLS_PER_WARP; ++c) {
        rp[c]  = (const uint4*)(d_rec + (size_t)(cbase + c) * CAP);
        cur[c] = rp[c][0];
        accA[c] = 0.f; accB[c] = 0.f;
    }

    for (int k = 0; k < nmax; ++k) {
#pragma unroll
        for (int c = 0; c < COLS_PER_WARP; ++c) {
            uint4 q = cur[c];
            cur[c] = rp[c][k + 1];         // prefetch (one-past-end lands in pad)
            term2(rowp, q.x, q.y, accA[c], accB[c]);
            term2(rowp, q.z, q.w, accA[c], accB[c]);
        }
    }

    // Stores: 4 consecutive cols -> one float4 per row of the pair.
    float* opA = out + (size_t)(rg * ROWS_PER_CTA + 2 * lane) * N_SP + cbase;
    float* opB = opA + N_SP;
    *(float4*)opA = make_float4(accA[0], accA[1], accA[2], accA[3]);
    *(float4*)opB = make_float4(accB[0], accB[1], accB[2], accB[3]);
}

// ---------------- launch ----------------

extern "C" void kernel_launch(void* const* d_in, const int* in_sizes, int n_in,
                              void* d_out, int out_size) {
    // metadata order: t_in, y_in, rates_1st, rates_2nd, den_norm,
    //                 inds_r1, inds_r2a, inds_r2b, inds_out1, inds_out2
    const float* y    = (const float*)d_in[1];
    const float* r1   = (const float*)d_in[2];
    const float* r2   = (const float*)d_in[3];
    const float* dn   = (const float*)d_in[4];
    const int*   ir1  = (const int*)d_in[5];
    const int*   ir2a = (const int*)d_in[6];
    const int*   ir2b = (const int*)d_in[7];
    const int*   io1  = (const int*)d_in[8];
    const int*   io2  = (const int*)d_in[9];
    float*       out  = (float*)d_out;

    int T1 = in_sizes[2];
    int T2 = in_sizes[3];
    int T  = T1 + T2;
    int B  = in_sizes[1] / N_SP;

    cudaFuncSetAttribute(mainK, cudaFuncAttributeMaxDynamicSharedMemorySize, SMEM_BYTES);

    // Zero cursors via a graph memset node (no extra kernel launch).
    void* curPtr = nullptr;
    cudaGetSymbolAddress(&curPtr, d_cursor);
    cudaMemsetAsync(curPtr, 0, N_SP * sizeof(int));

    scatterK<<<(T + 1023) / 1024, 256>>>(r1, r2, dn, ir1, ir2a, ir2b, io1, io2, T1, T2);
    mainK<<<(B / ROWS_PER_CTA) * C_SPLIT, 1024, SMEM_BYTES>>>(y, out);
}

// round 10
// speedup vs baseline: 1.0782x; 1.0782x over previous
#include <cuda_runtime.h>
#include <cuda_fp16.h>
#include <stdint.h>

// Problem constants (this problem: B=1024, N=1024, T1=20000, T2=60000)
#define N_SP      1024
#define STRIDE    1025                      // half2 units; 1025 % 32 == 1 -> conflict-free
#define CAP       256                       // fixed bucket capacity per species (mean 78)
#define ROWS_PER_CTA 64                     // 32 row-PAIRS, one pair per lane (half2)
#define PAIRS     32
#define C_SPLIT   8                         // column splits per row-group
#define COLS_PER_CTA  (N_SP / C_SPLIT)      // 128
#define COLS_PER_WARP (COLS_PER_CTA / 32)   // 4
#define SMEM_BYTES (PAIRS * STRIDE * 4)     // 131200 B (half2 = 4B)

// __device__ scratch (allocation-free per harness rules)
__device__ int d_cursor[N_SP];      // per-species fill count; re-zeroed at end of each run
__device__ int d_bar;               // grid barrier counter  (monotonic, never reset)
__device__ int d_t2;                // cursor-zero ticket    (monotonic, never reset)
// packed records: {rate_bits_f32, (ia*4) | (ib*4)<<16}.
// Slots >= cnt are NEVER written by any run (counts are input-determined) ->
// stay zero-initialized -> zero-rate pads are safe to read (contribute 0).
// +16 pad entries for one-past-end prefetch of the last slab.
__device__ __align__(16) uint2 d_rec[N_SP * CAP + 16];

__device__ __forceinline__ void term2(const char* rowp, uint32_t rate_bits,
                                      uint32_t off, float& accA, float& accB) {
    __half2 va = *(const __half2*)(rowp + (off & 0xFFFFu));
    __half2 vb = *(const __half2*)(rowp + (off >> 16));
    float2 pf = __half22float2(__hmul2(va, vb));
    float r = __uint_as_float(rate_bits);
    accA = fmaf(r, pf.x, accA);
    accB = fmaf(r, pf.y, accB);
}

// ---------------- fused kernel: scatter + fill + grid-barrier + gather -----------
// 128 co-resident CTAs (131KB smem -> 1 CTA/SM, 128 <= 148 SMs), so a software
// grid barrier is deadlock-free. Barrier counters are monotonic across graph
// replays (target derived from own arrival rank), so no reset is needed.

__global__ __launch_bounds__(1024, 1)
void fusedK(const float* __restrict__ y, float* __restrict__ out,
            const float* __restrict__ r1, const float* __restrict__ r2,
            const float* __restrict__ dn,
            const int* __restrict__ ir1,
            const int* __restrict__ ir2a, const int* __restrict__ ir2b,
            const int* __restrict__ io1, const int* __restrict__ io2,
            int T1, int T2) {
    extern __shared__ __align__(16) char smem_raw[];
    __half2* y_sh = (__half2*)smem_raw;     // PAIRS * STRIDE half2
    int tid  = threadIdx.x;
    int rg    = blockIdx.x / C_SPLIT;
    int cpart = blockIdx.x % C_SPLIT;
    int lane  = tid & 31, w = tid >> 5;
    int cbase = cpart * COLS_PER_CTA + w * COLS_PER_WARP;
    __shared__ int sflag_zero;

    // ---- Phase A: scatter (one term per thread; 131072 threads >= 80000 terms) ----
    int gt = blockIdx.x * 1024 + tid;
    int T = T1 + T2;
    if (gt < T) {
        float rate; int ia, ib, o;
        if (gt < T1) {           // 1st-order: y[ia] * 1.0 (constant slot at index N_SP)
            rate = r1[gt]; ia = ir1[gt]; ib = N_SP; o = io1[gt];
        } else {                 // 2nd-order: den_norm folded into rate
            int u = gt - T1;
            rate = r2[u] * dn[0]; ia = ir2a[u]; ib = ir2b[u]; o = io2[u];
        }
        int pos = atomicAdd(&d_cursor[o], 1);
        if (pos < CAP)           // capacity guard (never hit for this problem's stats)
            d_rec[o * CAP + pos] = make_uint2(__float_as_uint(rate),
                                              (uint32_t)(ia * 4) | ((uint32_t)(ib * 4) << 16));
    }

    // ---- Phase B: smem fill (overlaps Phase A's atomic latency) ----
    const float4* yb4 = (const float4*)(y + (size_t)rg * ROWS_PER_CTA * N_SP);
#pragma unroll
    for (int idx = tid; idx < PAIRS * N_SP / 4; idx += 1024) {
        int pair = idx >> 8;                       // 256 float4-slots per row
        int s4   = idx & 255;
        float4 a = yb4[(2 * pair)     * (N_SP / 4) + s4];
        float4 b = yb4[(2 * pair + 1) * (N_SP / 4) + s4];
        __half2* dst = y_sh + pair * STRIDE + s4 * 4;
        dst[0] = __floats2half2_rn(a.x, b.x);
        dst[1] = __floats2half2_rn(a.y, b.y);
        dst[2] = __floats2half2_rn(a.z, b.z);
        dst[3] = __floats2half2_rn(a.w, b.w);
    }
    if (tid < 32) y_sh[tid * STRIDE + N_SP] = __floats2half2_rn(1.f, 1.f);

    // ---- Phase C: grid barrier (monotonic counter; release/acquire fences) ----
    __threadfence();                                // publish records + cursors
    __syncthreads();
    if (tid == 0) {
        int arrive = atomicAdd(&d_bar, 1);          // rank in global arrival order
        int target = arrive - (arrive % (int)gridDim.x) + (int)gridDim.x;
        while (*(volatile int*)&d_bar < target) __nanosleep(64);
    }
    __syncthreads();
    __threadfence();                                // acquire

    // ---- Phase D prologue: read column counts; consume before zero-ticket ----
    int cnts[COLS_PER_WARP];
    int guard = 0;
#pragma unroll
    for (int cc = 0; cc < COLS_PER_WARP; ++cc) {
        int c = d_cursor[cbase + cc];
        guard |= c;
        cnts[cc] = c < CAP ? c : CAP;
    }
    if (guard == -1) out[0] = 0.f;                  // never true; forces load completion
    __syncthreads();                                // all threads' cursor reads done
    if (tid == 0) {
        int k = atomicAdd(&d_t2, 1);                // monotonic ticket
        sflag_zero = ((k % (int)gridDim.x) == (int)gridDim.x - 1);
    }
    __syncthreads();
    if (sflag_zero) d_cursor[tid] = 0;              // last CTA re-zeroes for next run

    // ---- Phase D: gather (round-8 champion loop) ----
    const char* rowp = (const char*)(y_sh + lane * STRIDE);
    float resA[COLS_PER_WARP], resB[COLS_PER_WARP];

    // Head prefetch for column 0 (uint4 = 2 packed records = 2 terms).
    const uint4* rp = (const uint4*)(d_rec + (size_t)cbase * CAP);
    uint4 h0 = rp[0], h1 = rp[1];

#pragma unroll
    for (int cc = 0; cc < COLS_PER_WARP; ++cc) {
        int cnt = cnts[cc];
        const uint4* rpn = (const uint4*)(d_rec + (size_t)(cbase + cc + 1) * CAP);
        uint4 a = h0, b = h1;
        if (cc + 1 < COLS_PER_WARP) { h0 = rpn[0]; h1 = rpn[1]; }  // next-column head

        int nq = cnt >> 2;                 // quads of 4 terms (2 uint4 each)
        float aA0 = 0.f, aB0 = 0.f, aA1 = 0.f, aB1 = 0.f;
        for (int k = 0; k < nq; ++k) {
            // prefetch next quad (one-past-end safe: slab-padded global)
            uint4 an = rp[2 * k + 2];
            uint4 bn = rp[2 * k + 3];
            term2(rowp, a.x, a.y, aA0, aB0);
            term2(rowp, a.z, a.w, aA1, aB1);
            term2(rowp, b.x, b.y, aA0, aB0);
            term2(rowp, b.z, b.w, aA1, aB1);
            a = an; b = bn;
        }
        // tail (<=3 terms)
        const uint2* rp2 = (const uint2*)rp;
        for (int k = nq * 4; k < cnt; ++k) {
            uint2 q = rp2[k];
            term2(rowp, q.x, q.y, aA0, aB0);
        }
        resA[cc] = aA0 + aA1;
        resB[cc] = aB0 + aB1;
        rp = rpn;
    }

    // Stores: 4 consecutive cols -> one float4 per row of the pair.
    float* opA = out + (size_t)(rg * ROWS_PER_CTA + 2 * lane) * N_SP + cbase;
    float* opB = opA + N_SP;
    *(float4*)opA = make_float4(resA[0], resA[1], resA[2], resA[3]);
    *(float4*)opB = make_float4(resB[0], resB[1], resB[2], resB[3]);
}

// ---------------- launch ----------------

extern "C" void kernel_launch(void* const* d_in, const int* in_sizes, int n_in,
                              void* d_out, int out_size) {
    // metadata order: t_in, y_in, rates_1st, rates_2nd, den_norm,
    //                 inds_r1, inds_r2a, inds_r2b, inds_out1, inds_out2
    const float* y    = (const float*)d_in[1];
    const float* r1   = (const float*)d_in[2];
    const float* r2   = (const float*)d_in[3];
    const float* dn   = (const float*)d_in[4];
    const int*   ir1  = (const int*)d_in[5];
    const int*   ir2a = (const int*)d_in[6];
    const int*   ir2b = (const int*)d_in[7];
    const int*   io1  = (const int*)d_in[8];
    const int*   io2  = (const int*)d_in[9];
    float*       out  = (float*)d_out;

    int T1 = in_sizes[2];
    int T2 = in_sizes[3];
    int B  = in_sizes[1] / N_SP;

    cudaFuncSetAttribute(fusedK, cudaFuncAttributeMaxDynamicSharedMemorySize, SMEM_BYTES);

    int grid = (B / ROWS_PER_CTA) * C_SPLIT;   // 128 CTAs: all co-resident (1/SM, <=148)
    fusedK<<<grid, 1024, SMEM_BYTES>>>(y, out, r1, r2, dn,
                                       ir1, ir2a, ir2b, io1, io2, T1, T2);
}